// round 15
// baseline (speedup 1.0000x reference)
#include <cuda_runtime.h>

#define T_LEN   8192
#define THREADS 1024
#define MOM     0.01f

// compile-time decay powers (folded from double)
constexpr double Dd    = 0.99;
constexpr double D2d   = Dd * Dd;
constexpr double D3d   = D2d * Dd;
constexpr double D4d   = D2d * D2d;
constexpr double D8d   = D4d * D4d;
constexpr double D16d  = D8d * D8d;
constexpr double D32d  = D16d * D16d;
constexpr double D64d  = D32d * D32d;
constexpr double D128d = D64d * D64d;
constexpr double D256d = D128d * D128d;

#define D1f   ((float)Dd)
#define D2f   ((float)D2d)
#define D3f   ((float)D3d)
#define D4f   ((float)D4d)
#define D8f   ((float)D8d)
#define D16f  ((float)D16d)
#define D32f  ((float)D32d)
#define D64f  ((float)D64d)
#define D128f ((float)D128d)
#define D256f ((float)D256d)

// ---- compile-time bias-correction table ----
// corr[t] = 1/(1 - 0.99^(t+1)); identically 1.0f in fp32 for t >= ~1724,
// so only the first 2048 entries are needed (warps 0..7 of each CTA).
#define CORR_N 2048
struct CorrTab { float v[CORR_N]; };
static constexpr CorrTab make_corr() {
    CorrTab t{};
    double q = 1.0;
    for (int i = 0; i < CORR_N; i++) {
        q *= 0.99;
        t.v[i] = (float)(1.0 / (1.0 - q));
    }
    return t;
}
__device__ constexpr CorrTab g_corr = make_corr();

__global__ __launch_bounds__(THREADS, 2)
void ema_kernel(const float* __restrict__ x, float* __restrict__ out) {
    const int tid  = threadIdx.x;
    const int lane = tid & 31;
    const int w    = tid >> 5;                 // warp 0..31, owns 256 contiguous elems
    const int seg  = w << 8;
    const long long rowbase = (long long)blockIdx.x * T_LEN + seg;

    const float4* __restrict__ xin = (const float4*)(x + rowbase);
    float4* __restrict__       xo  = (float4*)(out + rowbase);

    __shared__ float s_corr[CORR_N];   // staged copy of baked table
    __shared__ float s_c[32];

    // ---- front-batched loads: data (2 LDG.128) + table copy (1 LDG.64+STS.64) ----
    float4 vv[2];
#pragma unroll
    for (int k = 0; k < 2; k++) vv[k] = xin[k * 32 + lane];

    {   // 1024 threads x 1 float2 = 2048 floats; L2-hot broadcast
        float2 c = ((const float2*)g_corr.v)[tid];
        *(float2*)&s_corr[tid * 2] = c;
    }

    // d^(4*lane) via bit decomposition
    float dp4l = 1.0f;
    if (lane & 1)  dp4l *= D4f;
    if (lane & 2)  dp4l *= D8f;
    if (lane & 4)  dp4l *= D16f;
    if (lane & 8)  dp4l *= D32f;
    if (lane & 16) dp4l *= D64f;

    // ---- per-warp scan: 2 blocks of 128 elems, carry chained ----
    float carry = 0.0f;   // EMA value just before current block (uniform)
#pragma unroll
    for (int k = 0; k < 2; k++) {
        // local 4-elem EMA with zero carry-in
        float z0 = MOM * vv[k].x;
        float z1 = fmaf(D1f, z0, MOM * vv[k].y);
        float z2 = fmaf(D1f, z1, MOM * vv[k].z);
        float z3 = fmaf(D1f, z2, MOM * vv[k].w);

        // inclusive affine lane-scan of z3, transfer factor d^4
        float I = z3, u;
        u = __shfl_up_sync(0xffffffffu, I, 1);  if (lane >= 1)  I = fmaf(D4f,  u, I);
        u = __shfl_up_sync(0xffffffffu, I, 2);  if (lane >= 2)  I = fmaf(D8f,  u, I);
        u = __shfl_up_sync(0xffffffffu, I, 4);  if (lane >= 4)  I = fmaf(D16f, u, I);
        u = __shfl_up_sync(0xffffffffu, I, 8);  if (lane >= 8)  I = fmaf(D32f, u, I);
        u = __shfl_up_sync(0xffffffffu, I, 16); if (lane >= 16) I = fmaf(D64f, u, I);

        // exclusive prefix + block carry
        float E = __shfl_up_sync(0xffffffffu, I, 1);
        if (lane == 0) E = 0.0f;
        float F = fmaf(dp4l, carry, E);

        vv[k].x = fmaf(D1f, F, z0);
        vv[k].y = fmaf(D2f, F, z1);
        vv[k].z = fmaf(D3f, F, z2);
        vv[k].w = fmaf(D4f, F, z3);

        float I31 = __shfl_sync(0xffffffffu, I, 31);
        carry = fmaf(D128f, carry, I31);
    }

    // ---- cross-warp carry combine; barrier also orders s_corr copy ----
    if (lane == 0) s_c[w] = carry;
    __syncthreads();
    float cin = 0.0f;
    for (int ww = 0; ww < w; ww++)
        cin = fmaf(D256f, cin, s_c[ww]);

    // apply segment carry: v[128k+4l+i] += cin * d^(128k+4l+i+1)
    float g = cin * dp4l;
#pragma unroll
    for (int k = 0; k < 2; k++) {
        float h = (k == 0) ? g : g * D128f;
        vv[k].x = fmaf(h, D1f, vv[k].x);
        vv[k].y = fmaf(h, D2f, vv[k].y);
        vv[k].z = fmaf(h, D3f, vv[k].z);
        vv[k].w = fmaf(h, D4f, vv[k].w);
    }

    // ---- bias correction (t < 2048: warps 0..7) via smem table + store ----
    const bool needc = (seg < CORR_N);
#pragma unroll
    for (int k = 0; k < 2; k++) {
        float4 o = vv[k];
        if (needc) {
            float4 c = *(const float4*)&s_corr[seg + 128 * k + 4 * lane];
            o.x *= c.x; o.y *= c.y; o.z *= c.z; o.w *= c.w;
        }
        xo[k * 32 + lane] = o;
    }
}

extern "C" void kernel_launch(void* const* d_in, const int* in_sizes, int n_in,
                              void* d_out, int out_size) {
    const float* x   = (const float*)d_in[0];
    float*       out = (float*)d_out;
    const int rows   = in_sizes[0] / T_LEN;   // 8192

    ema_kernel<<<rows, THREADS>>>(x, out);
}

// round 16
// speedup vs baseline: 1.0852x; 1.0852x over previous
#include <cuda_runtime.h>

#define T_LEN   8192
#define THREADS 512
#define MOM     0.01f

// compile-time decay powers (folded from double)
constexpr double Dd    = 0.99;
constexpr double D2d   = Dd * Dd;
constexpr double D3d   = D2d * Dd;
constexpr double D4d   = D2d * D2d;
constexpr double D8d   = D4d * D4d;
constexpr double D16d  = D8d * D8d;
constexpr double D32d  = D16d * D16d;
constexpr double D64d  = D32d * D32d;
constexpr double D128d = D64d * D64d;
constexpr double D256d = D128d * D128d;
constexpr double D512d = D256d * D256d;

#define D1f   ((float)Dd)
#define D2f   ((float)D2d)
#define D3f   ((float)D3d)
#define D4f   ((float)D4d)
#define D8f   ((float)D8d)
#define D16f  ((float)D16d)
#define D32f  ((float)D32d)
#define D64f  ((float)D64d)
#define D128f ((float)D128d)
#define D512f ((float)D512d)

#define LOG2_D (-0.014499569695115089f)   // log2(0.99)

__global__ __launch_bounds__(THREADS, 3)
void ema_kernel(const float* __restrict__ x, float* __restrict__ out) {
    const int tid  = threadIdx.x;
    const int lane = tid & 31;
    const int w    = tid >> 5;                 // warp 0..15, owns 512 contiguous elems
    const int seg  = w << 9;
    const long long rowbase = (long long)blockIdx.x * T_LEN + seg;

    const float4* __restrict__ xin = (const float4*)(x + rowbase);
    float4* __restrict__       xo  = (float4*)(out + rowbase);

    // d^(4*lane) via bit decomposition
    float dp4l = 1.0f;
    if (lane & 1)  dp4l *= D4f;
    if (lane & 2)  dp4l *= D8f;
    if (lane & 4)  dp4l *= D16f;
    if (lane & 8)  dp4l *= D32f;
    if (lane & 16) dp4l *= D64f;

    // ---- load 4 blocks of 128, fully coalesced ----
    float4 vv[4];
#pragma unroll
    for (int k = 0; k < 4; k++) vv[k] = xin[k * 32 + lane];

    // ---- per-warp scan: 4 blocks of 128 elems, carry chained ----
    float carry = 0.0f;   // EMA value just before current block (uniform)
#pragma unroll
    for (int k = 0; k < 4; k++) {
        // local 4-elem EMA with zero carry-in
        float z0 = MOM * vv[k].x;
        float z1 = fmaf(D1f, z0, MOM * vv[k].y);
        float z2 = fmaf(D1f, z1, MOM * vv[k].z);
        float z3 = fmaf(D1f, z2, MOM * vv[k].w);

        // inclusive affine lane-scan of z3, transfer factor d^4
        float I = z3, u;
        u = __shfl_up_sync(0xffffffffu, I, 1);  if (lane >= 1)  I = fmaf(D4f,  u, I);
        u = __shfl_up_sync(0xffffffffu, I, 2);  if (lane >= 2)  I = fmaf(D8f,  u, I);
        u = __shfl_up_sync(0xffffffffu, I, 4);  if (lane >= 4)  I = fmaf(D16f, u, I);
        u = __shfl_up_sync(0xffffffffu, I, 8);  if (lane >= 8)  I = fmaf(D32f, u, I);
        u = __shfl_up_sync(0xffffffffu, I, 16); if (lane >= 16) I = fmaf(D64f, u, I);

        // exclusive prefix + block carry
        float E = __shfl_up_sync(0xffffffffu, I, 1);
        if (lane == 0) E = 0.0f;
        float F = fmaf(dp4l, carry, E);

        vv[k].x = fmaf(D1f, F, z0);
        vv[k].y = fmaf(D2f, F, z1);
        vv[k].z = fmaf(D3f, F, z2);
        vv[k].w = fmaf(D4f, F, z3);

        float I31 = __shfl_sync(0xffffffffu, I, 31);
        carry = fmaf(D128f, carry, I31);
    }

    // ---- cross-warp carry combine (16 floats smem, one barrier) ----
    __shared__ float s_c[16];
    if (lane == 0) s_c[w] = carry;
    __syncthreads();
    float cin = 0.0f;
    for (int ww = 0; ww < w; ww++)
        cin = fmaf(D512f, cin, s_c[ww]);

    // apply segment carry: v[128k+4l+i] += cin * d^(128k+4l+i+1)
    float g  = cin * dp4l;
    float fk = 1.0f;
#pragma unroll
    for (int k = 0; k < 4; k++) {
        float h = g * fk;
        vv[k].x = fmaf(h, D1f, vv[k].x);
        vv[k].y = fmaf(h, D2f, vv[k].y);
        vv[k].z = fmaf(h, D3f, vv[k].z);
        vv[k].w = fmaf(h, D4f, vv[k].w);
        fk *= D128f;
    }

    // ---- bias correction (t < 2048 only: warps 0..3) fused with store ----
    const bool needc = (seg < 2048);
#pragma unroll
    for (int k = 0; k < 4; k++) {
        float4 o = vv[k];
        if (needc) {
            float tb = (float)(seg + 128 * k + 4 * lane + 1);   // t+1 of o.x
            float qx = exp2f(LOG2_D * tb);
            float qy = exp2f(LOG2_D * (tb + 1.0f));
            float qz = exp2f(LOG2_D * (tb + 2.0f));
            float qw = exp2f(LOG2_D * (tb + 3.0f));
            o.x = __fdividef(o.x, 1.0f - qx);
            o.y = __fdividef(o.y, 1.0f - qy);
            o.z = __fdividef(o.z, 1.0f - qz);
            o.w = __fdividef(o.w, 1.0f - qw);
        }
        xo[k * 32 + lane] = o;
    }
}

extern "C" void kernel_launch(void* const* d_in, const int* in_sizes, int n_in,
                              void* d_out, int out_size) {
    const float* x   = (const float*)d_in[0];
    float*       out = (float*)d_out;
    const int rows   = in_sizes[0] / T_LEN;   // 8192

    ema_kernel<<<rows, THREADS>>>(x, out);
}